// round 2
// baseline (speedup 1.0000x reference)
#include <cuda_runtime.h>

#define BATCH 65536
#define NP 2048
#define NJ 292
#define ROWS_PER_BLOCK 16
#define NBLOCKS (BATCH / ROWS_PER_BLOCK)   /* 4096 */
#define NTHREADS 256
#define INV_SQRT2F 0.70710678118654752440f

// Per-block partial sums: [blk*8 + comp]
// comp 0..3 : SumA, SumBr, SumBi, SumC   (prob-weighted loss partial sums)
// comp 4..7 : sum(c_r), sum(c_r^2), sum(c_i), sum(c_i^2)  (moment sums)
__device__ float g_partials[NBLOCKS * 8];

__global__ __launch_bounds__(NTHREADS) void isi_main_kernel(
    const float* __restrict__ dnn,
    const float* __restrict__ bv,
    const float* __restrict__ hv,
    const float* __restrict__ xr,
    const float* __restrict__ xi,
    const float* __restrict__ isr,   // ISI_symbols_real (B,6)
    const float* __restrict__ isi,   // ISI_symbols_imag (B,6)
    const float* __restrict__ ich,   // ISI_channels     (B,6)
    const float* __restrict__ noise,
    const float* __restrict__ prob)
{
    __shared__ float srow[NP];        // one dnn row
    __shared__ float sprob[NJ];       // prob[878 + j]
    __shared__ float sred[8 * 8];     // warp partials: 8 warps x 8 comps

    const int tid  = threadIdx.x;
    const int blk  = blockIdx.x;
    const int row0 = blk * ROWS_PER_BLOCK;

    // Preload prob window (row-invariant)
    for (int j = tid; j < NJ; j += NTHREADS)
        sprob[j] = prob[878 + j];

    float sA = 0.f, sBr = 0.f, sBi = 0.f, sC = 0.f;
    float sM1r = 0.f, sM2r = 0.f, sM1i = 0.f, sM2i = 0.f;

    // Moment terms: one thread per row of this block (column 0 of (B,6) arrays)
    if (tid < ROWS_PER_BLOCK) {
        int r = row0 + tid;
        float c  = ich[(size_t)r * 6];
        float cr = c * isr[(size_t)r * 6];
        float ci = c * isi[(size_t)r * 6];
        sM1r = cr; sM2r = cr * cr;
        sM1i = ci; sM2i = ci * ci;
    }

    // Register prefetch of row 0 (2 float4 per thread = full 8KB row per block)
    const float4* src = (const float4*)(dnn + (size_t)row0 * NP);
    float4 v0 = src[tid];
    float4 v1 = src[tid + NTHREADS];

    for (int r = 0; r < ROWS_PER_BLOCK; ++r) {
        __syncthreads();                       // previous compute done (smem free)
        ((float4*)srow)[tid]            = v0;
        ((float4*)srow)[tid + NTHREADS] = v1;
        __syncthreads();

        // Prefetch next row while computing this one
        if (r + 1 < ROWS_PER_BLOCK) {
            const float4* nsrc = (const float4*)(dnn + (size_t)(row0 + r + 1) * NP);
            v0 = nsrc[tid];
            v1 = nsrc[tid + NTHREADS];
        }

        const int row = row0 + r;
        const float bb   = bv[row];
        const float bh   = bb * hv[row];
        const float xrr  = xr[row];
        const float xii  = xi[row];
        const float nz   = INV_SQRT2F * noise[row];
        const float ar_c = bh * xrr;           // A_r = ar_c*d0 + br_c
        const float ai_c = bh * xii;
        const float br_c = nz - xrr;
        const float bi_c = nz - xii;

        for (int j = tid; j < NJ; j += NTHREADS) {
            float d0 = srow[878 + j];
            float S  = srow[2 + j]    + srow[294 + j]  + srow[586 + j]
                     + srow[1170 + j] + srow[1462 + j] + srow[1754 + j];
            float a_r = fmaf(ar_c, d0, br_c);
            float a_i = fmaf(ai_c, d0, bi_c);
            float bS  = bb * S;
            float p   = sprob[j];
            sA  = fmaf(p, fmaf(a_r, a_r, a_i * a_i), sA);
            sBr = fmaf(p, a_r * bS, sBr);
            sBi = fmaf(p, a_i * bS, sBi);
            sC  = fmaf(p, bS * bS, sC);
        }
    }

    // Warp reduce 8 components
    const unsigned FULL = 0xFFFFFFFFu;
    #pragma unroll
    for (int o = 16; o > 0; o >>= 1) {
        sA   += __shfl_down_sync(FULL, sA, o);
        sBr  += __shfl_down_sync(FULL, sBr, o);
        sBi  += __shfl_down_sync(FULL, sBi, o);
        sC   += __shfl_down_sync(FULL, sC, o);
        sM1r += __shfl_down_sync(FULL, sM1r, o);
        sM2r += __shfl_down_sync(FULL, sM2r, o);
        sM1i += __shfl_down_sync(FULL, sM1i, o);
        sM2i += __shfl_down_sync(FULL, sM2i, o);
    }
    const int warp = tid >> 5, lane = tid & 31;
    if (lane == 0) {
        sred[warp * 8 + 0] = sA;   sred[warp * 8 + 1] = sBr;
        sred[warp * 8 + 2] = sBi;  sred[warp * 8 + 3] = sC;
        sred[warp * 8 + 4] = sM1r; sred[warp * 8 + 5] = sM2r;
        sred[warp * 8 + 6] = sM1i; sred[warp * 8 + 7] = sM2i;
    }
    __syncthreads();
    if (tid < 8) {
        float acc = 0.f;
        #pragma unroll
        for (int w = 0; w < 8; ++w) acc += sred[w * 8 + tid];
        g_partials[blk * 8 + tid] = acc;
    }
}

__global__ __launch_bounds__(256) void isi_final_kernel(float* __restrict__ out)
{
    __shared__ double dred[256];
    const int tid = threadIdx.x;

    double acc[8];
    #pragma unroll
    for (int c = 0; c < 8; ++c) acc[c] = 0.0;

    for (int b = tid; b < NBLOCKS; b += 256) {
        #pragma unroll
        for (int c = 0; c < 8; ++c)
            acc[c] += (double)g_partials[b * 8 + c];
    }

    double total[8];
    #pragma unroll
    for (int c = 0; c < 8; ++c) {
        dred[tid] = acc[c];
        __syncthreads();
        for (int s = 128; s > 0; s >>= 1) {
            if (tid < s) dred[tid] += dred[tid + s];
            __syncthreads();
        }
        if (tid == 0) total[c] = dred[0];
        __syncthreads();
    }

    if (tid == 0) {
        const double invB = 1.0 / (double)BATCH;
        double SumA  = total[0], SumBr = total[1];
        double SumBi = total[2], SumC  = total[3];
        double m1r = total[4] * invB, m2r = total[5] * invB;
        double m1i = total[6] * invB, m2i = total[7] * invB;
        double res = (SumA + 2.0 * m1r * SumBr + 2.0 * m1i * SumBi
                      + (m2r + m2i) * SumC) * invB;
        out[0] = (float)res;
    }
}

extern "C" void kernel_launch(void* const* d_in, const int* in_sizes, int n_in,
                              void* d_out, int out_size)
{
    const float* dnn   = (const float*)d_in[0];
    const float* bv    = (const float*)d_in[1];
    const float* hv    = (const float*)d_in[2];
    const float* xr    = (const float*)d_in[3];
    const float* xi    = (const float*)d_in[4];
    const float* isr   = (const float*)d_in[5];
    const float* isi   = (const float*)d_in[6];
    const float* ich   = (const float*)d_in[7];
    const float* noise = (const float*)d_in[8];
    const float* prob  = (const float*)d_in[9];
    float* out = (float*)d_out;

    isi_main_kernel<<<NBLOCKS, NTHREADS>>>(dnn, bv, hv, xr, xi, isr, isi, ich,
                                           noise, prob);
    isi_final_kernel<<<1, 256>>>(out);
}

// round 3
// speedup vs baseline: 1.0585x; 1.0585x over previous
#include <cuda_runtime.h>

#define BATCH 65536
#define NP 2048
#define NBLK 2048
#define RPB 32                     /* rows per block: 65536/2048 */
#define NT 160                     /* 5 warps; 146 active j-threads */
#define NJ2 146                    /* j pairs per row (292 j / 2) */
#define INV_SQRT2F 0.70710678118654752440f

// Per-block partial sums: [blk*8 + comp]
// 0..3 : SumA, SumBr, SumBi, SumC    4..7 : sum(c_r), sum(c_r^2), sum(c_i), sum(c_i^2)
__device__ float g_partials[NBLK * 8];
__device__ int   g_count = 0;

__global__ __launch_bounds__(NT) void isi_fused_kernel(
    const float* __restrict__ dnn,
    const float* __restrict__ bv,
    const float* __restrict__ hv,
    const float* __restrict__ xr,
    const float* __restrict__ xi,
    const float* __restrict__ isr,   // ISI_symbols_real (B,6)
    const float* __restrict__ isi,   // ISI_symbols_imag (B,6)
    const float* __restrict__ ich,   // ISI_channels     (B,6)
    const float* __restrict__ noise,
    const float* __restrict__ prob,
    float* __restrict__ out)
{
    const int tid  = threadIdx.x;
    const int blk  = blockIdx.x;
    const int row0 = blk * RPB;
    const bool act = (tid < NJ2);

    float sA = 0.f, sBr = 0.f, sBi = 0.f, sC = 0.f;
    float sM1r = 0.f, sM2r = 0.f, sM1i = 0.f, sM2i = 0.f;

    // Row-invariant prob pair for this thread's two j values (cols 878+2t, 879+2t)
    float2 p2 = make_float2(0.f, 0.f);
    if (act) p2 = ((const float2*)prob)[439 + tid];

    // Main streaming loop: each thread reads 7 float2 streams directly from GMEM.
    // No shared memory, no barriers -> iterations overlap, high MLP.
    for (int r = 0; r < RPB; ++r) {
        const int row = row0 + r;
        const float bb  = __ldg(bv + row);
        const float bh  = bb * __ldg(hv + row);
        const float xrr = __ldg(xr + row);
        const float xii = __ldg(xi + row);
        const float nz  = INV_SQRT2F * __ldg(noise + row);
        const float ar_c = bh * xrr;
        const float ai_c = bh * xii;
        const float br_c = nz - xrr;
        const float bi_c = nz - xii;

        if (act) {
            const float2* rp = (const float2*)(dnn + (size_t)row * NP);
            float2 s0 = rp[  1 + tid];   // col 2+j
            float2 s1 = rp[147 + tid];   // col 294+j
            float2 s2 = rp[293 + tid];   // col 586+j
            float2 d0 = rp[439 + tid];   // col 878+j  (center)
            float2 s3 = rp[585 + tid];   // col 1170+j
            float2 s4 = rp[731 + tid];   // col 1462+j
            float2 s5 = rp[877 + tid];   // col 1754+j

            // lane 0
            {
                float S  = s0.x + s1.x + s2.x + s3.x + s4.x + s5.x;
                float ar = fmaf(ar_c, d0.x, br_c);
                float ai = fmaf(ai_c, d0.x, bi_c);
                float bS = bb * S;
                float p  = p2.x;
                sA  = fmaf(p, fmaf(ar, ar, ai * ai), sA);
                sBr = fmaf(p, ar * bS, sBr);
                sBi = fmaf(p, ai * bS, sBi);
                sC  = fmaf(p, bS * bS, sC);
            }
            // lane 1
            {
                float S  = s0.y + s1.y + s2.y + s3.y + s4.y + s5.y;
                float ar = fmaf(ar_c, d0.y, br_c);
                float ai = fmaf(ai_c, d0.y, bi_c);
                float bS = bb * S;
                float p  = p2.y;
                sA  = fmaf(p, fmaf(ar, ar, ai * ai), sA);
                sBr = fmaf(p, ar * bS, sBr);
                sBi = fmaf(p, ai * bS, sBi);
                sC  = fmaf(p, bS * bS, sC);
            }
        }
    }

    // Moment terms: one thread per row of this block (column 0 of (B,6) arrays)
    if (tid < RPB) {
        int r = row0 + tid;
        float c  = __ldg(ich + (size_t)r * 6);
        float cr = c * __ldg(isr + (size_t)r * 6);
        float ci = c * __ldg(isi + (size_t)r * 6);
        sM1r = cr; sM2r = cr * cr;
        sM1i = ci; sM2i = ci * ci;
    }

    // Block reduction: warp shuffle then across 5 warps via smem
    __shared__ float sred[5 * 8];
    const unsigned FULL = 0xFFFFFFFFu;
    #pragma unroll
    for (int o = 16; o > 0; o >>= 1) {
        sA   += __shfl_down_sync(FULL, sA, o);
        sBr  += __shfl_down_sync(FULL, sBr, o);
        sBi  += __shfl_down_sync(FULL, sBi, o);
        sC   += __shfl_down_sync(FULL, sC, o);
        sM1r += __shfl_down_sync(FULL, sM1r, o);
        sM2r += __shfl_down_sync(FULL, sM2r, o);
        sM1i += __shfl_down_sync(FULL, sM1i, o);
        sM2i += __shfl_down_sync(FULL, sM2i, o);
    }
    const int warp = tid >> 5, lane = tid & 31;
    if (lane == 0) {
        sred[warp * 8 + 0] = sA;   sred[warp * 8 + 1] = sBr;
        sred[warp * 8 + 2] = sBi;  sred[warp * 8 + 3] = sC;
        sred[warp * 8 + 4] = sM1r; sred[warp * 8 + 5] = sM2r;
        sred[warp * 8 + 6] = sM1i; sred[warp * 8 + 7] = sM2i;
    }
    __syncthreads();
    if (tid < 8) {
        float acc = sred[tid] + sred[8 + tid] + sred[16 + tid]
                  + sred[24 + tid] + sred[32 + tid];
        g_partials[blk * 8 + tid] = acc;
    }

    // ---- last-block final combine (deterministic: fixed summation order) ----
    __shared__ int s_last;
    __threadfence();
    __syncthreads();
    if (tid == 0)
        s_last = (atomicAdd(&g_count, 1) == NBLK - 1);
    __syncthreads();
    if (!s_last) return;

    __threadfence();  // acquire: make all blocks' partials visible

    __shared__ double dsm[8 * NT];
    double acc[8];
    #pragma unroll
    for (int c = 0; c < 8; ++c) acc[c] = 0.0;
    for (int b = tid; b < NBLK; b += NT) {
        #pragma unroll
        for (int c = 0; c < 8; ++c)
            acc[c] += (double)g_partials[b * 8 + c];
    }
    #pragma unroll
    for (int c = 0; c < 8; ++c) dsm[c * NT + tid] = acc[c];
    __syncthreads();

    if (tid < 8) {
        double s = 0.0;
        for (int i = 0; i < NT; ++i) s += dsm[tid * NT + i];
        dsm[tid] = s;   // safe: all reads of row `tid` done by this thread
    }
    __syncthreads();
    if (tid == 0) {
        const double invB = 1.0 / (double)BATCH;
        double SumA  = dsm[0], SumBr = dsm[1], SumBi = dsm[2], SumC = dsm[3];
        double m1r = dsm[4] * invB, m2r = dsm[5] * invB;
        double m1i = dsm[6] * invB, m2i = dsm[7] * invB;
        out[0] = (float)((SumA + 2.0 * m1r * SumBr + 2.0 * m1i * SumBi
                          + (m2r + m2i) * SumC) * invB);
        g_count = 0;   // self-reset for next graph replay
    }
}

extern "C" void kernel_launch(void* const* d_in, const int* in_sizes, int n_in,
                              void* d_out, int out_size)
{
    const float* dnn   = (const float*)d_in[0];
    const float* bv    = (const float*)d_in[1];
    const float* hv    = (const float*)d_in[2];
    const float* xr    = (const float*)d_in[3];
    const float* xi    = (const float*)d_in[4];
    const float* isr   = (const float*)d_in[5];
    const float* isi   = (const float*)d_in[6];
    const float* ich   = (const float*)d_in[7];
    const float* noise = (const float*)d_in[8];
    const float* prob  = (const float*)d_in[9];

    isi_fused_kernel<<<NBLK, NT>>>(dnn, bv, hv, xr, xi, isr, isi, ich,
                                   noise, prob, (float*)d_out);
}